// round 6
// baseline (speedup 1.0000x reference)
#include <cuda_runtime.h>
#include <cstdint>

// ---------------- problem constants ----------------
#define FEAT     128
#define NNODES   512
#define BATCH    4
#define NSAMP    5
#define EEDGES   97920
#define OFFBASE  32896
#define TILE_M   64
#define H1P      33
#define NCHUNK   48
#define CHSZ     2040
#define NBS      (BATCH*NSAMP)

typedef unsigned long long ull;
typedef unsigned int u32;

__device__ float g_projA[BATCH*NNODES*FEAT];
__device__ float g_projB[BATCH*NNODES*FEAT];
__device__ float g_logits[BATCH*EEDGES];
__device__ float g_partZ[NBS*NCHUNK];
__device__ int   g_partE[NBS*NCHUNK];
__device__ int   g_arg[NBS];

static __device__ __forceinline__ ull splat2(float w) {
    ull r; u32 u = __float_as_uint(w);
    asm("mov.b64 %0, {%1, %2};" : "=l"(r) : "r"(u), "r"(u));
    return r;
}
static __device__ __forceinline__ ull fma2(ull a, ull b, ull c) {
    ull d;
    asm("fma.rn.f32x2 %0, %1, %2, %3;" : "=l"(d) : "l"(a), "l"(b), "l"(c));
    return d;
}
static __device__ __forceinline__ float2 unpack2(ull x) {
    u32 lo, hi;
    asm("mov.b64 {%0, %1}, %2;" : "=r"(lo), "=r"(hi) : "l"(x));
    return make_float2(__uint_as_float(lo), __uint_as_float(hi));
}

// ---------------- Threefry-2x32, key (0,42); scheme: out = x ^ y ------------
#define TF_ROUND(r) { x0 += x1; x1 = (x1 << (r)) | (x1 >> (32 - (r))); x1 ^= x0; }
static __device__ __forceinline__ u32 tf_xor(u32 x0, u32 x1) {
    const u32 k0 = 0u, k1 = 42u;
    const u32 ks2 = 0x1BD11BDAu ^ k0 ^ k1;
    x0 += k0; x1 += k1;
    TF_ROUND(13) TF_ROUND(15) TF_ROUND(26) TF_ROUND(6)
    x0 += k1; x1 += ks2 + 1u;
    TF_ROUND(17) TF_ROUND(29) TF_ROUND(16) TF_ROUND(24)
    x0 += ks2; x1 += k0 + 2u;
    TF_ROUND(13) TF_ROUND(15) TF_ROUND(26) TF_ROUND(6)
    x0 += k0; x1 += k1 + 3u;
    TF_ROUND(17) TF_ROUND(29) TF_ROUND(16) TF_ROUND(24)
    x0 += k1; x1 += ks2 + 4u;
    TF_ROUND(13) TF_ROUND(15) TF_ROUND(26) TF_ROUND(6)
    x0 += ks2; x1 += k0 + 5u;
    return x0 ^ x1;
}

static __device__ __forceinline__ float bits_to_gumbel(u32 bits) {
    float f = __uint_as_float((bits >> 9) | 0x3f800000u) - 1.0f;
    float u = fmaxf(f, 1.17549435e-38f);
    return -logf(-logf(u));
}

// ---------------- K1: per-node projections ----------------------------------
__global__ void k_proj(const float* __restrict__ nodes, const float* __restrict__ W1) {
    __shared__ float nrow[4][FEAT];
    const int tid = threadIdx.x, blk = blockIdx.x;
    const float* src = nodes + (size_t)blk * 4 * FEAT;
    for (int i = tid; i < 4 * FEAT; i += 256) ((float*)nrow)[i] = src[i];
    __syncthreads();
    const int half = tid >> 7, o = tid & 127;
    const float* w = W1 + half * FEAT * FEAT + o;
    float a0 = 0.f, a1 = 0.f, a2 = 0.f, a3 = 0.f;
#pragma unroll 8
    for (int k = 0; k < FEAT; k++) {
        float wv = w[k * FEAT];
        a0 = fmaf(nrow[0][k], wv, a0);
        a1 = fmaf(nrow[1][k], wv, a1);
        a2 = fmaf(nrow[2][k], wv, a2);
        a3 = fmaf(nrow[3][k], wv, a3);
    }
    float* dst = half ? g_projB : g_projA;
    int base = blk * 4 * FEAT + o;
    dst[base] = a0; dst[base + FEAT] = a1;
    dst[base + 2 * FEAT] = a2; dst[base + 3 * FEAT] = a3;
}

// ---------------- K2: edge MLP -> logits ------------------------------------
#define EDGE_SMEM_BYTES (16384 * 4 + FEAT * H1P * 8)

__global__ void __launch_bounds__(256, 2)
k_edge(const float* __restrict__ b1, const float* __restrict__ g1,
       const float* __restrict__ be1, const float* __restrict__ W2,
       const float* __restrict__ b2, const float* __restrict__ g2,
       const float* __restrict__ be2, const float* __restrict__ W3) {
    const int chunk = blockIdx.x;
    const int r = 257 + blockIdx.y;
    const int b = blockIdx.z;
    const int src0 = chunk * TILE_M;
    if (src0 >= r) return;
    const int nvalid = min(TILE_M, r - src0);

    extern __shared__ float smem[];
    float* w2s = smem;
    ull*  h1u  = (ull*)(smem + 16384);
    float* h1f = (float*)h1u;

    const int tid = threadIdx.x;
    const int lane = tid & 31, wid = tid >> 5;

    for (int i = tid; i < 16384; i += 256) w2s[i] = W2[i];

    float arow[4], g1r[4], be1r[4], b2r[4], g2r[4], be2r[4], w3r[4];
    const float* Arow = g_projA + ((b << 9) + r) * FEAT;
#pragma unroll
    for (int jj = 0; jj < 4; jj++) {
        int j = lane + 32 * jj;
        arow[jj] = Arow[j] + b1[j];
        g1r[jj] = g1[j];  be1r[jj] = be1[j];
        b2r[jj] = b2[j];  g2r[jj] = g2[j];
        be2r[jj] = be2[j]; w3r[jj] = W3[j];
    }

    for (int i = 0; i < 8; i++) {
        const int m = wid * 8 + i;
        float x[4];
        if (m < nvalid) {
            const float* Brow = g_projB + ((b << 9) + src0 + m) * FEAT;
#pragma unroll
            for (int jj = 0; jj < 4; jj++)
                x[jj] = fmaxf(arow[jj] + Brow[lane + 32 * jj], 0.f);
        } else {
#pragma unroll
            for (int jj = 0; jj < 4; jj++) x[jj] = 0.f;
        }
        float s = 0.f, q = 0.f;
#pragma unroll
        for (int jj = 0; jj < 4; jj++) { s += x[jj]; q = fmaf(x[jj], x[jj], q); }
#pragma unroll
        for (int off = 16; off; off >>= 1) {
            s += __shfl_xor_sync(0xffffffffu, s, off);
            q += __shfl_xor_sync(0xffffffffu, q, off);
        }
        const float mu = s * (1.f / FEAT);
        const float var = q * (1.f / FEAT) - mu * mu;
        const float rstd = rsqrtf(var + 1e-5f);
#pragma unroll
        for (int jj = 0; jj < 4; jj++) {
            int j = lane + 32 * jj;
            h1f[j * (2 * H1P) + m] = fmaf((x[jj] - mu) * rstd, g1r[jj], be1r[jj]);
        }
    }
    __syncthreads();

    const int tx = lane, ty = wid;
    ull acc[4][4];
#pragma unroll
    for (int p = 0; p < 4; p++)
#pragma unroll
        for (int ni = 0; ni < 4; ni++) acc[p][ni] = 0ull;

    const ull* ap = h1u + ty * 4;
    const float* wp = w2s + tx;
#pragma unroll 4
    for (int k = 0; k < FEAT; k++) {
        ull a0 = ap[0], a1 = ap[1], a2 = ap[2], a3 = ap[3];
        ull bb0 = splat2(wp[0]);
        ull bb1 = splat2(wp[32]);
        ull bb2 = splat2(wp[64]);
        ull bb3 = splat2(wp[96]);
        acc[0][0] = fma2(a0, bb0, acc[0][0]); acc[0][1] = fma2(a0, bb1, acc[0][1]);
        acc[0][2] = fma2(a0, bb2, acc[0][2]); acc[0][3] = fma2(a0, bb3, acc[0][3]);
        acc[1][0] = fma2(a1, bb0, acc[1][0]); acc[1][1] = fma2(a1, bb1, acc[1][1]);
        acc[1][2] = fma2(a1, bb2, acc[1][2]); acc[1][3] = fma2(a1, bb3, acc[1][3]);
        acc[2][0] = fma2(a2, bb0, acc[2][0]); acc[2][1] = fma2(a2, bb1, acc[2][1]);
        acc[2][2] = fma2(a2, bb2, acc[2][2]); acc[2][3] = fma2(a2, bb3, acc[2][3]);
        acc[3][0] = fma2(a3, bb0, acc[3][0]); acc[3][1] = fma2(a3, bb1, acc[3][1]);
        acc[3][2] = fma2(a3, bb2, acc[3][2]); acc[3][3] = fma2(a3, bb3, acc[3][3]);
        ap += H1P; wp += FEAT;
    }

    const int offr = (r * (r - 1)) / 2 - OFFBASE;
    float* lout = g_logits + b * EEDGES + offr + src0;
#pragma unroll
    for (int p = 0; p < 4; p++) {
        float2 lh[4];
#pragma unroll
        for (int ni = 0; ni < 4; ni++) lh[ni] = unpack2(acc[p][ni]);
#pragma unroll
        for (int h = 0; h < 2; h++) {
            const int m = ty * 8 + 2 * p + h;
            float v[4];
#pragma unroll
            for (int ni = 0; ni < 4; ni++)
                v[ni] = fmaxf((h ? lh[ni].y : lh[ni].x) + b2r[ni], 0.f);
            float s = 0.f, q = 0.f;
#pragma unroll
            for (int ni = 0; ni < 4; ni++) { s += v[ni]; q = fmaf(v[ni], v[ni], q); }
#pragma unroll
            for (int off = 16; off; off >>= 1) {
                s += __shfl_xor_sync(0xffffffffu, s, off);
                q += __shfl_xor_sync(0xffffffffu, q, off);
            }
            const float mu = s * (1.f / FEAT);
            const float var = q * (1.f / FEAT) - mu * mu;
            const float rstd = rsqrtf(var + 1e-5f);
            float d = 0.f;
#pragma unroll
            for (int ni = 0; ni < 4; ni++)
                d += fmaf((v[ni] - mu) * rstd, g2r[ni], be2r[ni]) * w3r[ni];
#pragma unroll
            for (int off = 16; off; off >>= 1)
                d += __shfl_xor_sync(0xffffffffu, d, off);
            if (tx == 0 && m < nvalid) lout[m] = d;
        }
    }
}

// ---------------- K3a: gumbel + partial argmax ------------------------------
__global__ void k_gumbel_part() {
    const int c = blockIdx.x;
    const int bs = blockIdx.y;
    const int b = bs / NSAMP;
    const int tid = threadIdx.x;
    const float* lg = g_logits + b * EEDGES;

    float bz = __int_as_float(0xff800000);
    int bestE = 0x7fffffff;

    for (int t = tid; t < CHSZ; t += 256) {
        const u32 e = (u32)(c * CHSZ + t);
        const u32 i = (u32)bs * (u32)EEDGES + e;
        float z = lg[e] + bits_to_gumbel(tf_xor(0u, i));
        if (z > bz || (z == bz && (int)e < bestE)) { bz = z; bestE = (int)e; }
    }

    __shared__ float zs[256];
    __shared__ int   es[256];
    zs[tid] = bz; es[tid] = bestE;
    __syncthreads();
    for (int st = 128; st; st >>= 1) {
        if (tid < st) {
            if (zs[tid + st] > zs[tid] ||
                (zs[tid + st] == zs[tid] && es[tid + st] < es[tid])) {
                zs[tid] = zs[tid + st]; es[tid] = es[tid + st];
            }
        }
        __syncthreads();
    }
    if (tid == 0) { g_partZ[bs * NCHUNK + c] = zs[0]; g_partE[bs * NCHUNK + c] = es[0]; }
}

__global__ void k_gumbel_final() {
    const int bs = threadIdx.x;
    if (bs >= NBS) return;
    float bz = __int_as_float(0xff800000);
    int bestE = 0;
    for (int c = 0; c < NCHUNK; c++) {
        float z = g_partZ[bs * NCHUNK + c];
        int   e = g_partE[bs * NCHUNK + c];
        if (z > bz || (z == bz && e < bestE)) { bz = z; bestE = e; }
    }
    g_arg[bs] = bestE;
}

// ---------------- K4: scatter selected edges ---------------------------------
__global__ void k_scatter(float* __restrict__ out) {
    const int t = threadIdx.x;
    if (t >= NBS) return;
    const int e = g_arg[t];
    const int v = e + OFFBASE;
    int r = (int)((1.0 + sqrt(8.0 * (double)v + 1.0)) * 0.5);
    while (r * (r - 1) / 2 > v) r--;
    while (r * (r + 1) / 2 <= v) r++;
    const int src = v - r * (r - 1) / 2;
    const int b = t / NSAMP;
    out[(size_t)b * NNODES * NNODES + r * NNODES + src] = 1.0f;
}

// ---------------- launch -----------------------------------------------------
extern "C" void kernel_launch(void* const* d_in, const int* in_sizes, int n_in,
                              void* d_out, int out_size) {
    const float* nodes = (const float*)d_in[0];
    const float* W1  = (const float*)d_in[1];
    const float* b1  = (const float*)d_in[2];
    const float* g1  = (const float*)d_in[3];
    const float* be1 = (const float*)d_in[4];
    const float* W2  = (const float*)d_in[5];
    const float* b2  = (const float*)d_in[6];
    const float* g2  = (const float*)d_in[7];
    const float* be2 = (const float*)d_in[8];
    const float* W3  = (const float*)d_in[9];
    float* out = (float*)d_out;

    cudaMemsetAsync(out, 0, (size_t)out_size * sizeof(float), 0);

    k_proj<<<(BATCH * NNODES) / 4, 256>>>(nodes, W1);

    cudaFuncSetAttribute(k_edge, cudaFuncAttributeMaxDynamicSharedMemorySize,
                         EDGE_SMEM_BYTES);
    dim3 eg(8, 255, BATCH);
    k_edge<<<eg, 256, EDGE_SMEM_BYTES>>>(b1, g1, be1, W2, b2, g2, be2, W3);

    dim3 gg(NCHUNK, NBS);
    k_gumbel_part<<<gg, 256>>>();
    k_gumbel_final<<<1, 32>>>();
    k_scatter<<<1, 32>>>(out);
}

// round 9
// speedup vs baseline: 1.6795x; 1.6795x over previous
#include <cuda_runtime.h>
#include <cuda_bf16.h>
#include <cstdint>
#include <cstring>

// ---------------- problem constants ----------------
#define FEAT     128
#define NNODES   512
#define BATCH    4
#define NSAMP    5
#define EEDGES   97920
#define OFFBASE  32896
#define NCHUNK   48
#define CHSZ     2040
#define NBS      (BATCH*NSAMP)
#define TILES    4080          // 4 batches * 255 r-values * 4 chunks of 128
#define NCTA     148

typedef unsigned long long ull;
typedef unsigned int u32;

// ---------------- device scratch ----------------
__device__ float g_projA[BATCH*NNODES*FEAT];
__device__ float g_projB[BATCH*NNODES*FEAT];
__device__ float g_logits[BATCH*EEDGES];
__device__ float g_partZ[NBS*NCHUNK];
__device__ int   g_partE[NBS*NCHUNK];
__device__ __align__(16) unsigned char g_Wimg[65536];  // Whi (32K), Wlo (32K), swizzled K-major Wt[n][k]

// ---------------- smem layout (bytes) ----------------
#define SM_WHI   0        // 32768
#define SM_WLO   32768    // 32768
#define SM_AHI   65536    // 32768
#define SM_ALO   98304    // 32768
#define SM_AROW  131072   // 512
#define SM_B1S   131584
#define SM_G1S   132096
#define SM_BE1S  132608
#define SM_B2S   133120
#define SM_GWS   133632
#define SM_SST1  134144   // [2][128] f32
#define SM_SST2  135168   // [2][128] f32
#define SM_SCAL  136192   // Sgw, Sbw
#define SMEM_TOTAL 136320

static __device__ __forceinline__ u32 smem_u32(const void* p) {
    u32 a;
    asm("{ .reg .u64 t; cvta.to.shared.u64 t, %1; cvt.u32.u64 %0, t; }" : "=r"(a) : "l"(p));
    return a;
}

#define LDSM4(r0,r1,r2,r3,addr) \
  asm volatile("ldmatrix.sync.aligned.m8n8.x4.shared.b16 {%0,%1,%2,%3}, [%4];" \
    : "=r"(r0),"=r"(r1),"=r"(r2),"=r"(r3) : "r"(addr))

#define MMA16816(d, a0,a1,a2,a3, b0,b1) \
  asm volatile("mma.sync.aligned.m16n8k16.row.col.f32.bf16.bf16.f32 " \
    "{%0,%1,%2,%3}, {%4,%5,%6,%7}, {%8,%9}, {%0,%1,%2,%3};" \
    : "+f"((d)[0]),"+f"((d)[1]),"+f"((d)[2]),"+f"((d)[3]) \
    : "r"(a0),"r"(a1),"r"(a2),"r"(a3), "r"(b0),"r"(b1))

// ---------------- Threefry / gumbel ----------------
#define TF_ROUND(r) { x0 += x1; x1 = (x1 << (r)) | (x1 >> (32 - (r))); x1 ^= x0; }
static __device__ __forceinline__ u32 tf_xor(u32 x0, u32 x1) {
    const u32 k0 = 0u, k1 = 42u;
    const u32 ks2 = 0x1BD11BDAu ^ k0 ^ k1;
    x0 += k0; x1 += k1;
    TF_ROUND(13) TF_ROUND(15) TF_ROUND(26) TF_ROUND(6)
    x0 += k1; x1 += ks2 + 1u;
    TF_ROUND(17) TF_ROUND(29) TF_ROUND(16) TF_ROUND(24)
    x0 += ks2; x1 += k0 + 2u;
    TF_ROUND(13) TF_ROUND(15) TF_ROUND(26) TF_ROUND(6)
    x0 += k0; x1 += k1 + 3u;
    TF_ROUND(17) TF_ROUND(29) TF_ROUND(16) TF_ROUND(24)
    x0 += k1; x1 += ks2 + 4u;
    TF_ROUND(13) TF_ROUND(15) TF_ROUND(26) TF_ROUND(6)
    x0 += ks2; x1 += k0 + 5u;
    return x0 ^ x1;
}
static __device__ __forceinline__ float bits_to_gumbel(u32 bits) {
    float f = __uint_as_float((bits >> 9) | 0x3f800000u) - 1.0f;
    float u = fmaxf(f, 1.17549435e-38f);
    return -logf(-logf(u));
}

// ---------------- K1: per-node projections ----------------------------------
__global__ void k_proj(const float* __restrict__ nodes, const float* __restrict__ W1) {
    __shared__ float nrow[4][FEAT];
    const int tid = threadIdx.x, blk = blockIdx.x;
    const float* src = nodes + (size_t)blk * 4 * FEAT;
    for (int i = tid; i < 4 * FEAT; i += 256) ((float*)nrow)[i] = src[i];
    __syncthreads();
    const int half = tid >> 7, o = tid & 127;
    const float* w = W1 + half * FEAT * FEAT + o;
    float a0 = 0.f, a1 = 0.f, a2 = 0.f, a3 = 0.f;
#pragma unroll 8
    for (int k = 0; k < FEAT; k++) {
        float wv = w[k * FEAT];
        a0 = fmaf(nrow[0][k], wv, a0);
        a1 = fmaf(nrow[1][k], wv, a1);
        a2 = fmaf(nrow[2][k], wv, a2);
        a3 = fmaf(nrow[3][k], wv, a3);
    }
    float* dst = half ? g_projB : g_projA;
    int base = blk * 4 * FEAT + o;
    dst[base] = a0; dst[base + FEAT] = a1;
    dst[base + 2 * FEAT] = a2; dst[base + 3 * FEAT] = a3;
}

// ---------------- K1b: W2 -> bf16 hi/lo Wt[n][k] swizzled image --------------
__global__ void k_wprep(const float* __restrict__ W2) {
    const int idx = blockIdx.x * 256 + threadIdx.x;   // 0..16383
    const int k = idx >> 7, n = idx & 127;
    const float w = W2[k * FEAT + n];
    __nv_bfloat16 hb = __float2bfloat16(w);
    float lo = w - __bfloat162float(hb);
    __nv_bfloat16 lb = __float2bfloat16(lo);
    const u32 off = (u32)(n * 256) + (((u32)(k * 2)) ^ ((u32)(n & 7) << 4));
    unsigned short hbits, lbits;
    memcpy(&hbits, &hb, 2); memcpy(&lbits, &lb, 2);
    *(unsigned short*)(g_Wimg + off) = hbits;
    *(unsigned short*)(g_Wimg + 32768 + off) = lbits;
}

// ---------------- K2: persistent mma.sync edge-MLP ---------------------------
__global__ void __launch_bounds__(256, 1)
k_edge_mma(const float* __restrict__ b1, const float* __restrict__ g1,
           const float* __restrict__ be1, const float* __restrict__ b2,
           const float* __restrict__ g2, const float* __restrict__ be2,
           const float* __restrict__ W3) {
    extern __shared__ __align__(1024) char smem[];
    const u32 sb = smem_u32(smem);
    float* smf = (float*)smem;
    const int tid = threadIdx.x;
    const int lane = tid & 31, w = tid >> 5;

    // ---- one-time init ----
    {
        const uint4* src = (const uint4*)g_Wimg;
        uint4* dst = (uint4*)smem;
        for (int i = tid; i < 4096; i += 256) dst[i] = src[i];
    }
    if (tid < 128) {
        smf[SM_B1S/4 + tid]  = b1[tid];
        smf[SM_G1S/4 + tid]  = g1[tid];
        smf[SM_BE1S/4 + tid] = be1[tid];
        smf[SM_B2S/4 + tid]  = b2[tid];
        smf[SM_GWS/4 + tid]  = g2[tid] * W3[tid];
    }
    __syncthreads();
    if (tid == 0) {
        float sg = 0.f, sbw = 0.f;
        for (int j = 0; j < 128; j++) {
            sg  += smf[SM_GWS/4 + j];
            sbw += be2[j] * W3[j];
        }
        smf[SM_SCAL/4 + 0] = sg;
        smf[SM_SCAL/4 + 1] = sbw;
    }
    __syncthreads();

    const float* g1s  = smf + SM_G1S/4;
    const float* be1s = smf + SM_BE1S/4;
    float* arows = smf + SM_AROW/4;
    float* sst1  = smf + SM_SST1/4;
    float* sst2  = smf + SM_SST2/4;

    // lane geometry for ldmatrix (A and B share swz since row&7 == lane&7)
    const u32 swz = (u32)(lane & 7) << 4;
    const u32 a_rowoff = (u32)(16*w + (lane & 7) + ((lane >> 3) & 1) * 8) * 256;
    const u32 akc = (u32)((lane >> 4) & 1) * 16;
    const u32 b_rowin = (u32)(((lane >> 4) & 1) * 8 + (lane & 7)) * 256;
    const u32 bkc = (u32)((lane >> 3) & 1) * 16;
    const u32 aHIb = sb + SM_AHI + a_rowoff;
    const u32 aLOb = sb + SM_ALO + a_rowoff;
    const u32 wHIb = sb + SM_WHI + b_rowin;
    const u32 wLOb = sb + SM_WLO + b_rowin;

    for (int t = blockIdx.x; t < TILES; t += NCTA) {
        const int b  = t / 1020;
        const int rm = t - b * 1020;
        const int r  = 257 + (rm >> 2);
        const int c  = rm & 3;
        const int src0 = c << 7;
        if (src0 >= r) continue;
        const int nvalid = min(128, r - src0);

        if (tid < 128)
            arows[tid] = g_projA[(((size_t)(b << 9) + r) << 7) + tid] + smf[SM_B1S/4 + tid];
        __syncthreads();

        // ---- phase 1: relu + LN, bf16 hi/lo -> swizzled smem A tiles ----
        const int m = tid & 127, h = tid >> 7;
        const bool valid = m < nvalid;
        float x[64];
        float S1p = 0.f, S2p = 0.f;
        if (valid) {
            const float4* bp = (const float4*)(g_projB + (((size_t)(b << 9) + src0 + m) << 7) + (h << 6));
#pragma unroll
            for (int q = 0; q < 16; q++) {
                float4 v4 = bp[q];
                const int j0 = q * 4;
                x[j0+0] = fmaxf(arows[h*64 + j0+0] + v4.x, 0.f);
                x[j0+1] = fmaxf(arows[h*64 + j0+1] + v4.y, 0.f);
                x[j0+2] = fmaxf(arows[h*64 + j0+2] + v4.z, 0.f);
                x[j0+3] = fmaxf(arows[h*64 + j0+3] + v4.w, 0.f);
                S1p += x[j0+0] + x[j0+1] + x[j0+2] + x[j0+3];
                S2p = fmaf(x[j0+0], x[j0+0], S2p); S2p = fmaf(x[j0+1], x[j0+1], S2p);
                S2p = fmaf(x[j0+2], x[j0+2], S2p); S2p = fmaf(x[j0+3], x[j0+3], S2p);
            }
        } else {
#pragma unroll
            for (int q = 0; q < 64; q++) x[q] = 0.f;
        }
        sst1[h*128 + m] = S1p; sst2[h*128 + m] = S2p;
        __syncthreads();
        const float S1 = sst1[m] + sst1[128 + m];
        const float S2 = sst2[m] + sst2[128 + m];
        const float mu = S1 * (1.f/128.f);
        const float var = S2 * (1.f/128.f) - mu * mu;
        const float rstd = rsqrtf(var + 1e-5f);

        const u32 mswz = (u32)(m & 7) << 4;
#pragma unroll
        for (int q = 0; q < 8; q++) {
            u32 hu[4], lu[4];
#pragma unroll
            for (int pp = 0; pp < 4; pp++) {
                const int j0 = q*8 + pp*2;
                const int j  = h*64 + j0;
                float y0 = 0.f, y1 = 0.f;
                if (valid) {
                    y0 = fmaf((x[j0]   - mu) * rstd, g1s[j],   be1s[j]);
                    y1 = fmaf((x[j0+1] - mu) * rstd, g1s[j+1], be1s[j+1]);
                }
                __nv_bfloat162 hb = __floats2bfloat162_rn(y0, y1);
                float r0 = y0 - __bfloat162float(hb.x);
                float r1 = y1 - __bfloat162float(hb.y);
                __nv_bfloat162 lb = __floats2bfloat162_rn(r0, r1);
                memcpy(&hu[pp], &hb, 4); memcpy(&lu[pp], &lb, 4);
            }
            const u32 off = (u32)(m * 256) + (((u32)(h*128 + q*16)) ^ mswz);
            *(uint4*)(smem + SM_AHI + off) = make_uint4(hu[0], hu[1], hu[2], hu[3]);
            *(uint4*)(smem + SM_ALO + off) = make_uint4(lu[0], lu[1], lu[2], lu[3]);
        }
        __syncthreads();

        // ---- GEMM: D = Ahi*Whi + Alo*Whi + Ahi*Wlo  (register accumulators) ----
        float acc[64];
#pragma unroll
        for (int i = 0; i < 64; i++) acc[i] = 0.f;

        for (int s = 0; s < 8; s++) {
            const u32 aoff = ((u32)(s*32) + akc) ^ swz;
            const u32 boff = ((u32)(s*32) + bkc) ^ swz;
            u32 ah0,ah1,ah2,ah3, al0,al1,al2,al3;
            LDSM4(ah0,ah1,ah2,ah3, aHIb + aoff);
            LDSM4(al0,al1,al2,al3, aLOb + aoff);
#pragma unroll
            for (int u = 0; u < 8; u++) {
                u32 bh0,bh1,bh2,bh3, bl0,bl1,bl2,bl3;
                LDSM4(bh0,bh1,bh2,bh3, wHIb + (u32)(u*4096) + boff);
                LDSM4(bl0,bl1,bl2,bl3, wLOb + (u32)(u*4096) + boff);
                MMA16816(acc + u*8,     ah0,ah1,ah2,ah3, bh0,bh1);
                MMA16816(acc + u*8 + 4, ah0,ah1,ah2,ah3, bh2,bh3);
                MMA16816(acc + u*8,     al0,al1,al2,al3, bh0,bh1);
                MMA16816(acc + u*8 + 4, al0,al1,al2,al3, bh2,bh3);
                MMA16816(acc + u*8,     ah0,ah1,ah2,ah3, bl0,bl1);
                MMA16816(acc + u*8 + 4, ah0,ah1,ah2,ah3, bl2,bl3);
            }
        }

        // ---- epilogue in registers: relu + LN stats + W3 dot ----
        float S1a=0.f,S2a=0.f,Swa=0.f, S1b=0.f,S2b=0.f,Swb=0.f;
        const int tq = (lane & 3) * 2;
#pragma unroll
        for (int nt = 0; nt < 16; nt++) {
            const int base = (nt >> 1) * 8 + (nt & 1) * 4;
            const int j0 = nt * 8 + tq;
            float2 b2p = *(float2*)(smem + SM_B2S + j0*4);
            float2 gwp = *(float2*)(smem + SM_GWS + j0*4);
            float v0 = fmaxf(acc[base+0] + b2p.x, 0.f);
            float v1 = fmaxf(acc[base+1] + b2p.y, 0.f);
            float v2 = fmaxf(acc[base+2] + b2p.x, 0.f);
            float v3 = fmaxf(acc[base+3] + b2p.y, 0.f);
            S1a += v0 + v1; S2a = fmaf(v0,v0,fmaf(v1,v1,S2a)); Swa = fmaf(gwp.x,v0,fmaf(gwp.y,v1,Swa));
            S1b += v2 + v3; S2b = fmaf(v2,v2,fmaf(v3,v3,S2b)); Swb = fmaf(gwp.x,v2,fmaf(gwp.y,v3,Swb));
        }
#pragma unroll
        for (int o = 1; o <= 2; o <<= 1) {
            S1a += __shfl_xor_sync(0xffffffffu, S1a, o);
            S2a += __shfl_xor_sync(0xffffffffu, S2a, o);
            Swa += __shfl_xor_sync(0xffffffffu, Swa, o);
            S1b += __shfl_xor_sync(0xffffffffu, S1b, o);
            S2b += __shfl_xor_sync(0xffffffffu, S2b, o);
            Swb += __shfl_xor_sync(0xffffffffu, Swb, o);
        }
        if ((lane & 3) == 0) {
            const float Sgw = smf[SM_SCAL/4 + 0], Sbw = smf[SM_SCAL/4 + 1];
            const int offr = (r * (r - 1)) / 2 - OFFBASE + src0;
            const int rowA = 16*w + (lane >> 2);
            {
                const float mu2 = S1a * (1.f/128.f);
                const float var2 = S2a * (1.f/128.f) - mu2 * mu2;
                const float rs2 = rsqrtf(var2 + 1e-5f);
                if (rowA < nvalid)
                    g_logits[b * EEDGES + offr + rowA] = rs2 * (Swa - mu2 * Sgw) + Sbw;
            }
            {
                const int rowB = rowA + 8;
                const float mu2 = S1b * (1.f/128.f);
                const float var2 = S2b * (1.f/128.f) - mu2 * mu2;
                const float rs2 = rsqrtf(var2 + 1e-5f);
                if (rowB < nvalid)
                    g_logits[b * EEDGES + offr + rowB] = rs2 * (Swb - mu2 * Sgw) + Sbw;
            }
        }
        __syncthreads();
    }
}

// ---------------- K3a: gumbel + partial argmax ------------------------------
__global__ void k_gumbel_part() {
    const int c = blockIdx.x;
    const int bs = blockIdx.y;
    const int b = bs / NSAMP;
    const int tid = threadIdx.x;
    const float* lg = g_logits + b * EEDGES;

    float bz = __int_as_float(0xff800000);
    int bestE = 0x7fffffff;

    for (int t = tid; t < CHSZ; t += 256) {
        const u32 e = (u32)(c * CHSZ + t);
        const u32 i = (u32)bs * (u32)EEDGES + e;
        float z = lg[e] + bits_to_gumbel(tf_xor(0u, i));
        if (z > bz || (z == bz && (int)e < bestE)) { bz = z; bestE = (int)e; }
    }

    __shared__ float zs[256];
    __shared__ int   es[256];
    zs[tid] = bz; es[tid] = bestE;
    __syncthreads();
    for (int st = 128; st; st >>= 1) {
        if (tid < st) {
            if (zs[tid + st] > zs[tid] ||
                (zs[tid + st] == zs[tid] && es[tid + st] < es[tid])) {
                zs[tid] = zs[tid + st]; es[tid] = es[tid + st];
            }
        }
        __syncthreads();
    }
    if (tid == 0) { g_partZ[bs * NCHUNK + c] = zs[0]; g_partE[bs * NCHUNK + c] = es[0]; }
}

// ---------------- K3b+K4: final argmax + scatter -----------------------------
__global__ void k_final_scatter(float* __restrict__ out) {
    const int t = threadIdx.x;
    if (t >= NBS) return;
    float bz = __int_as_float(0xff800000);
    int bestE = 0;
    for (int c = 0; c < NCHUNK; c++) {
        float z = g_partZ[t * NCHUNK + c];
        int   e = g_partE[t * NCHUNK + c];
        if (z > bz || (z == bz && e < bestE)) { bz = z; bestE = e; }
    }
    const int v = bestE + OFFBASE;
    int r = (int)((1.0 + sqrt(8.0 * (double)v + 1.0)) * 0.5);
    while (r * (r - 1) / 2 > v) r--;
    while (r * (r + 1) / 2 <= v) r++;
    const int src = v - r * (r - 1) / 2;
    const int b = t / NSAMP;
    out[(size_t)b * NNODES * NNODES + r * NNODES + src] = 1.0f;
}

// ---------------- launch -----------------------------------------------------
extern "C" void kernel_launch(void* const* d_in, const int* in_sizes, int n_in,
                              void* d_out, int out_size) {
    const float* nodes = (const float*)d_in[0];
    const float* W1  = (const float*)d_in[1];
    const float* b1  = (const float*)d_in[2];
    const float* g1  = (const float*)d_in[3];
    const float* be1 = (const float*)d_in[4];
    const float* W2  = (const float*)d_in[5];
    const float* b2  = (const float*)d_in[6];
    const float* g2  = (const float*)d_in[7];
    const float* be2 = (const float*)d_in[8];
    const float* W3  = (const float*)d_in[9];
    float* out = (float*)d_out;

    cudaMemsetAsync(out, 0, (size_t)out_size * sizeof(float), 0);

    k_proj<<<(BATCH * NNODES) / 4, 256>>>(nodes, W1);
    k_wprep<<<64, 256>>>(W2);

    cudaFuncSetAttribute(k_edge_mma, cudaFuncAttributeMaxDynamicSharedMemorySize,
                         SMEM_TOTAL);
    k_edge_mma<<<NCTA, 256, SMEM_TOTAL>>>(b1, g1, be1, b2, g2, be2, W3);

    dim3 gg(NCHUNK, NBS);
    k_gumbel_part<<<gg, 256>>>();
    k_final_scatter<<<1, 32>>>(out);
}